// round 16
// baseline (speedup 1.0000x reference)
#include <cuda_runtime.h>
#include <cstdint>

#define Hh 56
#define Ww 56
#define HO 58
#define WO 58
#define PLANE_IN  3136           // 56*56
#define PLANE_OUT 3364           // 58*58
#define PLANE_BYTES (PLANE_IN * 4)     // 12544
#define PAIR_ELEMS  (2 * PLANE_IN)     // 6272
#define PAIR_BYTES  (2 * PLANE_BYTES)  // 25088, multiple of 16
// C fixed at 128 by the generator
#define C_LOG2 7
#define C_MASK 127

// dynamic smem: buf[2][PAIR_ELEMS] then 2 mbarriers
#define SMEM_BYTES (2 * PAIR_BYTES + 16)

__device__ __forceinline__ uint32_t smem_u32(const void* p) {
    uint32_t a;
    asm("{ .reg .u64 t; cvta.to.shared.u64 t, %1; cvt.u32.u64 %0, t; }"
        : "=r"(a) : "l"(p));
    return a;
}

__device__ __forceinline__ void mbar_wait(uint32_t mbar, int phase) {
    asm volatile(
        "{\n\t"
        ".reg .pred P;\n\t"
        "WAIT_%=:\n\t"
        "mbarrier.try_wait.parity.acquire.cta.shared::cta.b64 P, [%0], %1, 0x989680;\n\t"
        "@P bra.uni DONE_%=;\n\t"
        "bra.uni WAIT_%=;\n\t"
        "DONE_%=:\n\t"
        "}"
        :: "r"(mbar), "r"(phase) : "memory");
}

__device__ __forceinline__ void tma_issue_pair(uint32_t dst, const float* src, uint32_t mbar) {
    asm volatile(
        "mbarrier.arrive.expect_tx.shared.b64 _, [%0], %1;"
        :: "r"(mbar), "r"((uint32_t)PAIR_BYTES) : "memory");
    asm volatile(
        "cp.async.bulk.shared::cta.global.mbarrier::complete_tx::bytes [%0], [%1], %2, [%3];"
        :: "r"(dst), "l"(src), "r"((uint32_t)PAIR_BYTES), "r"(mbar) : "memory");
}

__global__ void __launch_bounds__(512, 4)
weight_pad2d_kernel(const float* __restrict__ x,
                    const float* __restrict__ topW,
                    const float* __restrict__ botW,
                    const float* __restrict__ leftW,
                    const float* __restrict__ rightW,
                    const float* __restrict__ topleftW,
                    const float* __restrict__ toprightW,
                    const float* __restrict__ botleftW,
                    const float* __restrict__ botrightW,
                    const int* __restrict__ num_patches_ptr,
                    int npairs,
                    float* __restrict__ out)
{
    extern __shared__ __align__(16) char smraw[];
    float* __restrict__ buf0 = (float*)smraw;
    float* __restrict__ buf1 = buf0 + PAIR_ELEMS;
    unsigned long long* mbarp = (unsigned long long*)(buf1 + PAIR_ELEMS);

    const int tid  = threadIdx.x;
    const int warp = tid >> 5;           // 0..15
    const int grp  = warp >> 3;          // 0,1 : which plane of the pair
    const int w    = warp & 7;           // row-group within plane
    const int lane = tid & 31;

    const int P  = *num_patches_ptr;
    const int PP = P * P;

    const uint32_t mb[2] = { smem_u32(&mbarp[0]), smem_u32(&mbarp[1]) };
    float* const bufs[2] = { buf0, buf1 };
    const uint32_t bufaddr[2] = { smem_u32(buf0), smem_u32(buf1) };

    if (tid == 0) {
        asm volatile("mbarrier.init.shared.b64 [%0], 1;" :: "r"(mb[0]) : "memory");
        asm volatile("mbarrier.init.shared.b64 [%0], 1;" :: "r"(mb[1]) : "memory");
        asm volatile("fence.proxy.async.shared::cta;" ::: "memory");
    }
    __syncthreads();

    const bool ld = (lane < 28);   // lanes 0..27 read SMEM
    const bool st = (lane < 29);   // lanes 0..28 store

    int pair = blockIdx.x;
    // prologue: fetch first pair into buf0
    if (tid == 0 && pair < npairs) {
        tma_issue_pair(bufaddr[0], x + (size_t)pair * PAIR_ELEMS, mb[0]);
    }

    int ph0 = 0, ph1 = 0;
    int it = 0;
    for (; pair < npairs; pair += gridDim.x, ++it) {
        const int cur = it & 1;
        const int npair = pair + gridDim.x;

        // issue next pair into the other buffer (consumed last iteration,
        // reads fenced by the trailing __syncthreads)
        if (tid == 0 && npair < npairs) {
            tma_issue_pair(bufaddr[cur ^ 1], x + (size_t)npair * PAIR_ELEMS, mb[cur ^ 1]);
        }

        // this warp-group's plane + masks (overlaps TMA)
        const int plane = 2 * pair + grp;
        const int bidx = plane >> C_LOG2;
        const int ch   = plane & C_MASK;
        const unsigned q1 = (unsigned)bidx / (unsigned)P;
        const int colp    = bidx - (int)(q1 * (unsigned)P);       // bidx % P
        const unsigned q2 = (unsigned)bidx / (unsigned)PP;
        const int within  = bidx - (int)(q2 * (unsigned)PP);      // bidx % PP
        const bool topz   = within < P;
        const bool botz   = within >= PP - P;
        const bool leftz  = colp == 0;
        const bool rightz = colp == (P - 1);

        const float wLr = leftz  ? 0.0f : leftW[ch];
        const float wRr = rightz ? 0.0f : rightW[ch];

        // wait for current buffer to be full
        if (cur == 0) { mbar_wait(mb[0], ph0); ph0 ^= 1; }
        else          { mbar_wait(mb[1], ph1); ph1 ^= 1; }

        const float* __restrict__ S = bufs[cur] + grp * PLANE_IN;
        float*       __restrict__ op = out + (size_t)plane * PLANE_OUT;

        // ---- interior rows r = 1..56: one warp per row; aligned LDS.64 + 2 shfl ----
        #pragma unroll
        for (int k = 0; k < 7; k++) {
            const int r = 1 + w + 8 * k;
            float2 g = make_float2(0.0f, 0.0f);
            if (ld) g = *(const float2*)(S + (r - 1) * Ww + 2 * lane);
            const float upx = __shfl_up_sync(0xffffffffu, g.x, 1);
            const float upy = __shfl_up_sync(0xffffffffu, g.y, 1);
            if (st) {
                const float o_lo = (lane == 0)  ? wLr * (g.x + g.y) : upy;
                const float o_hi = (lane == 28) ? wRr * (upx + upy) : g.x;
                *(float2*)(op + r * WO + 2 * lane) = make_float2(o_lo, o_hi);
            }
        }

        // ---- top row r=0 (w==0; SMEM rows 0,1) ----
        if (w == 0) {
            float2 g0 = make_float2(0.0f, 0.0f), g1 = make_float2(0.0f, 0.0f);
            if (ld) {
                g0 = *(const float2*)(S + 2 * lane);
                g1 = *(const float2*)(S + Ww + 2 * lane);
            }
            const float wT = topz ? 0.0f : topW[ch];
            const float tl = (topz || leftz)  ? 0.0f : topleftW[ch];
            const float tr = (topz || rightz) ? 0.0f : toprightW[ch];
            const float2 h = make_float2(g0.x + g1.x, g0.y + g1.y);
            const float hup   = __shfl_up_sync(0xffffffffu, h.y, 1);
            const float g0yup = __shfl_up_sync(0xffffffffu, g0.y, 1);
            if (st) {
                const float o_lo = (lane == 0)  ? tl * g0.x : wT * hup;
                const float o_hi = (lane == 28) ? tr * g0yup : wT * h.x;
                *(float2*)(op + 2 * lane) = make_float2(o_lo, o_hi);
            }
        }

        // ---- bottom row r=57 (w==7; SMEM rows 55(gb), 54(ga)) ----
        if (w == 7) {
            float2 gb = make_float2(0.0f, 0.0f), ga = make_float2(0.0f, 0.0f);
            if (ld) {
                gb = *(const float2*)(S + (Hh - 1) * Ww + 2 * lane);
                ga = *(const float2*)(S + (Hh - 2) * Ww + 2 * lane);
            }
            const float wB = botz ? 0.0f : botW[ch];
            const float bl = (botz || leftz)  ? 0.0f : botleftW[ch];
            const float br = (botz || rightz) ? 0.0f : botrightW[ch];
            const float2 h = make_float2(gb.x + ga.x, gb.y + ga.y);
            const float hup   = __shfl_up_sync(0xffffffffu, h.y, 1);
            const float gbyup = __shfl_up_sync(0xffffffffu, gb.y, 1);
            if (st) {
                const float o_lo = (lane == 0)  ? bl * gb.x : wB * hup;
                const float o_hi = (lane == 28) ? br * gbyup : wB * h.x;
                *(float2*)(op + (HO - 1) * WO + 2 * lane) = make_float2(o_lo, o_hi);
            }
        }

        // all reads of buf[cur] done before it is refilled next iteration
        __syncthreads();
    }
}

extern "C" void kernel_launch(void* const* d_in, const int* in_sizes, int n_in,
                              void* d_out, int out_size)
{
    const float* x         = (const float*)d_in[0];
    const float* topW      = (const float*)d_in[1];
    const float* botW      = (const float*)d_in[2];
    const float* leftW     = (const float*)d_in[3];
    const float* rightW    = (const float*)d_in[4];
    const float* topleftW  = (const float*)d_in[5];
    const float* toprightW = (const float*)d_in[6];
    const float* botleftW  = (const float*)d_in[7];
    const float* botrightW = (const float*)d_in[8];
    const int*   num_patches = (const int*)d_in[10];

    const int planes = in_sizes[0] / PLANE_IN;   // b * C = 16384 (even)
    const int npairs = planes / 2;               // 8192

    static int attr_set = 0;
    if (!attr_set) {
        cudaFuncSetAttribute(weight_pad2d_kernel,
                             cudaFuncAttributeMaxDynamicSharedMemorySize, SMEM_BYTES);
        attr_set = 1;
    }

    int grid = 148 * 4;
    if (grid > npairs) grid = npairs;

    weight_pad2d_kernel<<<grid, 512, SMEM_BYTES>>>(
        x, topW, botW, leftW, rightW,
        topleftW, toprightW, botleftW, botrightW,
        num_patches, npairs, (float*)d_out);
}

// round 17
// speedup vs baseline: 1.0558x; 1.0558x over previous
#include <cuda_runtime.h>
#include <cstdint>

#define Hh 56
#define Ww 56
#define HO 58
#define WO 58
#define PLANE_IN  3136           // 56*56
#define PLANE_OUT 3364           // 58*58
#define PLANE_BYTES (PLANE_IN * 4)   // 12544, multiple of 16
// C fixed at 128 by the generator
#define C_LOG2 7
#define C_MASK 127

__device__ __forceinline__ uint32_t smem_u32(const void* p) {
    uint32_t a;
    asm("{ .reg .u64 t; cvta.to.shared.u64 t, %1; cvt.u32.u64 %0, t; }"
        : "=r"(a) : "l"(p));
    return a;
}

__device__ __forceinline__ void mbar_wait(uint32_t mbar, int phase) {
    asm volatile(
        "{\n\t"
        ".reg .pred P;\n\t"
        "WAIT_%=:\n\t"
        "mbarrier.try_wait.parity.acquire.cta.shared::cta.b64 P, [%0], %1, 0x989680;\n\t"
        "@P bra.uni DONE_%=;\n\t"
        "bra.uni WAIT_%=;\n\t"
        "DONE_%=:\n\t"
        "}"
        :: "r"(mbar), "r"(phase) : "memory");
}

__device__ __forceinline__ void tma_issue(uint32_t dst, const float* src, uint32_t mbar) {
    asm volatile(
        "mbarrier.arrive.expect_tx.shared.b64 _, [%0], %1;"
        :: "r"(mbar), "r"((uint32_t)PLANE_BYTES) : "memory");
    asm volatile(
        "cp.async.bulk.shared::cta.global.mbarrier::complete_tx::bytes [%0], [%1], %2, [%3];"
        :: "r"(dst), "l"(src), "r"((uint32_t)PLANE_BYTES), "r"(mbar) : "memory");
}

struct __align__(16) Smem {
    float buf[2][PLANE_IN];
    unsigned long long mbar[2];
};

__global__ void __launch_bounds__(256, 8)
weight_pad2d_kernel(const float* __restrict__ x,
                    const float* __restrict__ topW,
                    const float* __restrict__ botW,
                    const float* __restrict__ leftW,
                    const float* __restrict__ rightW,
                    const float* __restrict__ topleftW,
                    const float* __restrict__ toprightW,
                    const float* __restrict__ botleftW,
                    const float* __restrict__ botrightW,
                    const int* __restrict__ num_patches_ptr,
                    int planes,
                    float* __restrict__ out)
{
    __shared__ Smem sm;

    const int tid  = threadIdx.x;
    const int warp = tid >> 5;           // 0..7
    const int lane = tid & 31;

    const int P  = *num_patches_ptr;
    const int PP = P * P;

    const uint32_t mb[2] = { smem_u32(&sm.mbar[0]), smem_u32(&sm.mbar[1]) };
    const uint32_t bufaddr[2] = { smem_u32(&sm.buf[0][0]), smem_u32(&sm.buf[1][0]) };

    if (tid == 0) {
        asm volatile("mbarrier.init.shared.b64 [%0], 1;" :: "r"(mb[0]) : "memory");
        asm volatile("mbarrier.init.shared.b64 [%0], 1;" :: "r"(mb[1]) : "memory");
        asm volatile("fence.proxy.async.shared::cta;" ::: "memory");
    }
    __syncthreads();

    const bool ld = (lane < 28);   // lanes 0..27 read SMEM
    const bool st = (lane < 29);   // lanes 0..28 store

    const int gstride = gridDim.x;
    int plane = blockIdx.x;
    // prologue: fetch first plane into buf[0]
    if (tid == 0 && plane < planes) {
        tma_issue(bufaddr[0], x + (size_t)plane * PLANE_IN, mb[0]);
    }

    int ph0 = 0, ph1 = 0;     // full-barrier phases (tid 0 only uses them)
    int it = 0;
    for (; plane < planes; plane += gstride, ++it) {
        const int cur = it & 1;
        const int nplane = plane + gstride;

        // masks / weights — overlaps the in-flight TMA and tid0's wait
        const int bidx = plane >> C_LOG2;
        const int ch   = plane & C_MASK;
        const unsigned q1 = (unsigned)bidx / (unsigned)P;
        const int colp    = bidx - (int)(q1 * (unsigned)P);       // bidx % P
        const unsigned q2 = (unsigned)bidx / (unsigned)PP;
        const int within  = bidx - (int)(q2 * (unsigned)PP);      // bidx % PP
        const bool topz   = within < P;
        const bool botz   = within >= PP - P;
        const bool leftz  = colp == 0;
        const bool rightz = colp == (P - 1);

        const float wLr = leftz  ? 0.0f : leftW[ch];
        const float wRr = rightz ? 0.0f : rightW[ch];

        // elected waiter: only tid0 polls the mbarrier; the bar.sync both
        // publishes "cur is full" and proves "everyone is done with cur^1"
        if (tid == 0) {
            if (cur == 0) { mbar_wait(mb[0], ph0); ph0 ^= 1; }
            else          { mbar_wait(mb[1], ph1); ph1 ^= 1; }
        }
        __syncthreads();

        // refill the other buffer (its readers all passed the sync above);
        // TMA runs while this plane is consumed
        if (tid == 0 && nplane < planes) {
            tma_issue(bufaddr[cur ^ 1], x + (size_t)nplane * PLANE_IN, mb[cur ^ 1]);
        }

        const float* __restrict__ S = sm.buf[cur];
        float*       __restrict__ op = out + (size_t)plane * PLANE_OUT;

        // ---- interior rows r = 1..56: one warp per row; aligned LDS.64 + 2 shfl ----
        #pragma unroll
        for (int k = 0; k < 7; k++) {
            const int r = 1 + warp + 8 * k;
            float2 g = make_float2(0.0f, 0.0f);
            if (ld) g = *(const float2*)(S + (r - 1) * Ww + 2 * lane);
            const float upx = __shfl_up_sync(0xffffffffu, g.x, 1);
            const float upy = __shfl_up_sync(0xffffffffu, g.y, 1);
            if (st) {
                const float o_lo = (lane == 0)  ? wLr * (g.x + g.y) : upy;
                const float o_hi = (lane == 28) ? wRr * (upx + upy) : g.x;
                *(float2*)(op + r * WO + 2 * lane) = make_float2(o_lo, o_hi);
            }
        }

        // ---- top row r=0 (warp 0; SMEM rows 0,1) ----
        if (warp == 0) {
            float2 g0 = make_float2(0.0f, 0.0f), g1 = make_float2(0.0f, 0.0f);
            if (ld) {
                g0 = *(const float2*)(S + 2 * lane);
                g1 = *(const float2*)(S + Ww + 2 * lane);
            }
            const float wT = topz ? 0.0f : topW[ch];
            const float tl = (topz || leftz)  ? 0.0f : topleftW[ch];
            const float tr = (topz || rightz) ? 0.0f : toprightW[ch];
            const float2 h = make_float2(g0.x + g1.x, g0.y + g1.y);
            const float hup   = __shfl_up_sync(0xffffffffu, h.y, 1);
            const float g0yup = __shfl_up_sync(0xffffffffu, g0.y, 1);
            if (st) {
                const float o_lo = (lane == 0)  ? tl * g0.x : wT * hup;
                const float o_hi = (lane == 28) ? tr * g0yup : wT * h.x;
                *(float2*)(op + 2 * lane) = make_float2(o_lo, o_hi);
            }
        }

        // ---- bottom row r=57 (warp 7; SMEM rows 55(gb), 54(ga)) ----
        if (warp == 7) {
            float2 gb = make_float2(0.0f, 0.0f), ga = make_float2(0.0f, 0.0f);
            if (ld) {
                gb = *(const float2*)(S + (Hh - 1) * Ww + 2 * lane);
                ga = *(const float2*)(S + (Hh - 2) * Ww + 2 * lane);
            }
            const float wB = botz ? 0.0f : botW[ch];
            const float bl = (botz || leftz)  ? 0.0f : botleftW[ch];
            const float br = (botz || rightz) ? 0.0f : botrightW[ch];
            const float2 h = make_float2(gb.x + ga.x, gb.y + ga.y);
            const float hup   = __shfl_up_sync(0xffffffffu, h.y, 1);
            const float gbyup = __shfl_up_sync(0xffffffffu, gb.y, 1);
            if (st) {
                const float o_lo = (lane == 0)  ? bl * gb.x : wB * hup;
                const float o_hi = (lane == 28) ? br * gbyup : wB * h.x;
                *(float2*)(op + (HO - 1) * WO + 2 * lane) = make_float2(o_lo, o_hi);
            }
        }
        // no trailing sync needed: next iteration's bar.sync (after tid0's
        // full-wait) fences these reads before buf[cur] is refilled
    }
}

extern "C" void kernel_launch(void* const* d_in, const int* in_sizes, int n_in,
                              void* d_out, int out_size)
{
    const float* x         = (const float*)d_in[0];
    const float* topW      = (const float*)d_in[1];
    const float* botW      = (const float*)d_in[2];
    const float* leftW     = (const float*)d_in[3];
    const float* rightW    = (const float*)d_in[4];
    const float* topleftW  = (const float*)d_in[5];
    const float* toprightW = (const float*)d_in[6];
    const float* botleftW  = (const float*)d_in[7];
    const float* botrightW = (const float*)d_in[8];
    const int*   num_patches = (const int*)d_in[10];

    const int planes = in_sizes[0] / PLANE_IN;   // b * C = 16384

    int grid = 148 * 8;
    if (grid > planes) grid = planes;

    weight_pad2d_kernel<<<grid, 256>>>(
        x, topW, botW, leftW, rightW,
        topleftW, toprightW, botleftW, botrightW,
        num_patches, planes, (float*)d_out);
}